// round 11
// baseline (speedup 1.0000x reference)
#include <cuda_runtime.h>
#include <cuda_bf16.h>
#include <cstdint>

#define NUM_EMBEDS 8192
#define EMBED_DIM  256
#define BATCH      16
#define TLEN       1024
#define NVEC       (BATCH * TLEN)             /* 16384 */
#define ZQ_ELEMS   (BATCH * EMBED_DIM * TLEN) /* 4194304 */
#define CAP        64

/* ---- scratch ---- */
__device__ float          g_cn2[NUM_EMBEDS];
__device__ float          g_wrow[NVEC];
__device__ int            g_cnmax_i;
__device__ int            g_ccount[NVEC];
__device__ int            g_cand[NVEC * CAP];
__device__ int            g_idx[NVEC];
__device__ int            g_counts[NUM_EMBEDS];
__device__ float          g_loss_part[256];
__device__ float          g_perp_part[32];
__device__ float          g_zet[NVEC * EMBED_DIM];         /* z_e transposed fp32 */
__device__ __nv_bfloat16  g_zbf[NVEC * EMBED_DIM];         /* z_e transposed bf16 */
__device__ __nv_bfloat16  g_cbf[NUM_EMBEDS * EMBED_DIM];   /* codebook bf16 */

/* ============================ helpers ============================ */
__device__ __forceinline__ uint32_t smem_u32(const void* p) {
    uint32_t a;
    asm("{ .reg .u64 t; cvta.to.shared.u64 t, %1; cvt.u32.u64 %0, t; }" : "=r"(a) : "l"(p));
    return a;
}
__device__ __forceinline__ unsigned enc_f(float f) {
    unsigned u = __float_as_uint(f);
    return (u & 0x80000000u) ? ~u : (u | 0x80000000u);
}
__device__ __forceinline__ float dec_f(unsigned u) {
    return (u & 0x80000000u) ? __uint_as_float(u ^ 0x80000000u) : __uint_as_float(~u);
}
__device__ __forceinline__ unsigned pack_bf2(float a, float b) {
    __nv_bfloat162 h = __floats2bfloat162_rn(a, b);
    return *(unsigned*)&h;
}

#define LDSM4(r, addr)                                                          \
    asm volatile("ldmatrix.sync.aligned.m8n8.x4.shared.b16 {%0,%1,%2,%3}, [%4];"\
        : "=r"((r)[0]), "=r"((r)[1]), "=r"((r)[2]), "=r"((r)[3]) : "r"(addr))

#define MMA_BF16(d, a, b)                                                       \
    asm volatile("mma.sync.aligned.m16n8k16.row.col.f32.bf16.bf16.f32 "         \
        "{%0,%1,%2,%3}, {%4,%5,%6,%7}, {%8,%9}, {%0,%1,%2,%3};"                 \
        : "+f"((d)[0]), "+f"((d)[1]), "+f"((d)[2]), "+f"((d)[3])                \
        : "r"((a)[0]), "r"((a)[1]), "r"((a)[2]), "r"((a)[3]),                   \
          "r"((b)[0]), "r"((b)[1]))

#define CP_ASYNC16(dst, src)                                                    \
    asm volatile("cp.async.cg.shared.global [%0], [%1], 16;" :: "r"(dst), "l"(src))
#define CP_COMMIT()  asm volatile("cp.async.commit_group;" ::: "memory")
#define CP_WAIT(n)   asm volatile("cp.async.wait_group %0;" :: "n"(n) : "memory")
#define BAR_G(id)    asm volatile("bar.sync %0, 128;" :: "r"(id) : "memory")

/* ================= P0: reset cnmax (graph-replay determinism) ================= */
__global__ void init_kernel() {
    if (threadIdx.x == 0) g_cnmax_i = 0;
}

/* ================= P1: codebook -> bf16, cn2, max ================= */
__global__ __launch_bounds__(256)
void cb_prep_kernel(const float* __restrict__ codebook) {
    int lane = threadIdx.x & 31;
    int code = blockIdx.x * 8 + (threadIdx.x >> 5);   /* grid 1024 */
    const float4* src = (const float4*)(codebook + (size_t)code * EMBED_DIM);
    float4 v0 = src[lane * 2], v1 = src[lane * 2 + 1];
    float s = v0.x*v0.x + v0.y*v0.y + v0.z*v0.z + v0.w*v0.w
            + v1.x*v1.x + v1.y*v1.y + v1.z*v1.z + v1.w*v1.w;
    uint4 u;
    u.x = pack_bf2(v0.x, v0.y); u.y = pack_bf2(v0.z, v0.w);
    u.z = pack_bf2(v1.x, v1.y); u.w = pack_bf2(v1.z, v1.w);
    ((uint4*)(g_cbf + (size_t)code * EMBED_DIM))[lane] = u;
#pragma unroll
    for (int o = 16; o; o >>= 1) s += __shfl_xor_sync(0xffffffffu, s, o);
    if (lane == 0) {
        g_cn2[code] = s;
        atomicMax(&g_cnmax_i, __float_as_int(s));
        g_counts[code] = 0;
    }
}

/* ================= P2: z_e transpose (fp32+bf16) + xnorm + window ================= */
__global__ __launch_bounds__(256)
void ze_prep_kernel(const float* __restrict__ z_e) {
    __shared__ float s[64][65];
    __shared__ float xn[4][64];
    int n0 = blockIdx.x * 64;
    int b  = n0 >> 10, t0 = n0 & 1023;
    int tx = threadIdx.x & 63, ty = threadIdx.x >> 6;
    float part = 0.f;

    for (int d0 = 0; d0 < EMBED_DIM; d0 += 64) {
        const float* src = z_e + ((size_t)b * EMBED_DIM + d0) * TLEN + t0;
#pragma unroll
        for (int j = 0; j < 16; ++j) {
            int dl = j * 4 + ty;
            s[dl][tx] = src[(size_t)dl * TLEN + tx];
        }
        __syncthreads();
#pragma unroll
        for (int j = 0; j < 16; ++j) {
            int nl = j * 4 + ty;
            float v = s[tx][nl];
            g_zet[(size_t)(n0 + nl) * EMBED_DIM + d0 + tx] = v;
            g_zbf[(size_t)(n0 + nl) * EMBED_DIM + d0 + tx] = __float2bfloat16_rn(v);
        }
#pragma unroll
        for (int j = 0; j < 16; ++j) {
            float v = s[ty * 16 + j][tx];
            part = fmaf(v, v, part);
        }
        __syncthreads();
    }
    xn[ty][tx] = part;
    __syncthreads();
    if (ty == 0) {
        float x2 = xn[0][tx] + xn[1][tx] + xn[2][tx] + xn[3][tx];
        float cnmax = __int_as_float(g_cnmax_i);
        g_wrow[n0 + tx] = 0.035f * sqrtf(x2) * sqrtf(cnmax) + 0.5f;
    }
}

/* ================= K2: persistent dual-group bf16 screening GEMM =================
 * 128 CTAs, 8 warps = 2 independent 4-warp groups, shared resident A (128x256).
 * Group g owns codes [g*4096, (g+1)*4096) as 64 double-buffered chunks of 64.
 * Mainloop = R8's compiler-scheduled form (no manual ping-pong).
 * Epilogue reorder: barrier right after mainloop, then cp.async for chunk i+2
 * (flight covers the epilogue), then convert/min/append with no 2nd barrier.
 */
#define STRH       264                       /* smem row stride halves (528 B) */
#define A_BYTES    (128 * STRH * 2)          /* 67584 */
#define BBUF_BYTES (64 * STRH * 2)           /* 33792 */
#define SM_B(g, b) (A_BYTES + (g) * 2 * BBUF_BYTES + (b) * BBUF_BYTES)
#define SM_STAT    (A_BYTES + 4 * BBUF_BYTES)   /* 202752 */
#define SMEM_GEMM  (SM_STAT + 1024)

__global__ __launch_bounds__(256, 1)
void gemm_screen_kernel() {
    extern __shared__ char sm[];
    uint32_t sb = smem_u32(sm);
    unsigned* s_amin = (unsigned*)(sm + SM_STAT);
    int*      s_cnt  = (int*)(sm + SM_STAT + 512);

    int tid = threadIdx.x, lane = tid & 31, warp = tid >> 5;
    int g  = warp >> 2;          /* group 0/1 */
    int gw = warp & 3;           /* warp in group */
    int wm = gw >> 1, wn = gw & 1;
    int gt = tid & 127;          /* thread in group */
    int bar = 1 + g;
    int bx = blockIdx.x;

    if (tid < 128) { s_amin[tid] = 0xFFFFFFFFu; s_cnt[tid] = 0; }

    /* prologue: A (all threads) + group's B chunks 0,1 */
    {
        const __nv_bfloat16* xa = g_zbf + (size_t)(bx * 128) * EMBED_DIM;
#pragma unroll
        for (int q = 0; q < 16; ++q) {
            int v = tid + q * 256;           /* 0..4095 */
            int row = v >> 5, c = v & 31;
            CP_ASYNC16(sb + (uint32_t)(row * STRH + c * 8) * 2,
                       (const char*)(xa + (size_t)row * EMBED_DIM + c * 8));
        }
        CP_COMMIT();
#pragma unroll
        for (int b = 0; b < 2; ++b) {
            const __nv_bfloat16* cb = g_cbf + (size_t)(g * 64 + b) * 64 * EMBED_DIM;
            uint32_t dstb = sb + SM_B(g, b);
#pragma unroll
            for (int q = 0; q < 16; ++q) {
                int v = gt + q * 128;        /* 0..2047 */
                int row = v >> 5, c = v & 31;
                CP_ASYNC16(dstb + (uint32_t)(row * STRH + c * 8) * 2,
                           (const char*)(cb + (size_t)row * EMBED_DIM + c * 8));
            }
            CP_COMMIT();
        }
        CP_WAIT(1);              /* A + own B0 complete (B1 may fly) */
        __syncthreads();
    }

    /* per-thread row windows */
    float ww[8];
#pragma unroll
    for (int mi = 0; mi < 4; ++mi)
#pragma unroll
        for (int h = 0; h < 2; ++h)
            ww[mi * 2 + h] = g_wrow[bx * 128 + wm * 64 + mi * 16 + (lane >> 2) + h * 8];

    for (int i = 0; i < 64; ++i) {
        if (i) {
            if (i < 63) CP_WAIT(1); else CP_WAIT(0);
            BAR_G(bar);          /* whole group's B(i) visible */
        }
        uint32_t Bs = sb + SM_B(g, i & 1);

        float acc[4][4][4];
#pragma unroll
        for (int mi = 0; mi < 4; ++mi)
#pragma unroll
            for (int ni = 0; ni < 4; ++ni)
#pragma unroll
                for (int r = 0; r < 4; ++r) acc[mi][ni][r] = 0.f;

        /* ---- R8 mainloop: let ptxas pipeline ---- */
#pragma unroll
        for (int kk = 0; kk < 16; ++kk) {
            uint32_t a[4][4], bfr[4][2];
#pragma unroll
            for (int mi = 0; mi < 4; ++mi) {
                uint32_t addr = sb + (uint32_t)((wm * 64 + mi * 16 + (lane & 15)) * STRH
                                 + (lane >> 4) * 8 + kk * 16) * 2;
                LDSM4(a[mi], addr);
            }
#pragma unroll
            for (int pp = 0; pp < 2; ++pp) {
                uint32_t r4[4];
                uint32_t addr = Bs + (uint32_t)((wn * 32 + pp * 16 + (lane & 7)
                                 + ((lane >> 4) & 1) * 8) * STRH
                                 + ((lane >> 3) & 1) * 8 + kk * 16) * 2;
                LDSM4(r4, addr);
                bfr[2 * pp][0] = r4[0];     bfr[2 * pp][1] = r4[1];
                bfr[2 * pp + 1][0] = r4[2]; bfr[2 * pp + 1][1] = r4[3];
            }
#pragma unroll
            for (int mi = 0; mi < 4; ++mi)
#pragma unroll
                for (int ni = 0; ni < 4; ++ni)
                    MMA_BF16(acc[mi][ni], a[mi], bfr[ni]);
        }

        BAR_G(bar);              /* all group ldsm of buffer (i&1) done */

        /* issue next-next chunk load immediately: flight covers epilogue */
        if (i < 62) {
            const __nv_bfloat16* cb = g_cbf + (size_t)(g * 64 + i + 2) * 64 * EMBED_DIM;
            uint32_t dstb = sb + SM_B(g, i & 1);
#pragma unroll
            for (int q = 0; q < 16; ++q) {
                int v = gt + q * 128;
                int row = v >> 5, c = v & 31;
                CP_ASYNC16(dstb + (uint32_t)(row * STRH + c * 8) * 2,
                           (const char*)(cb + (size_t)row * EMBED_DIM + c * 8));
            }
            CP_COMMIT();
        }

        /* ---- epilogue: dist overwrites acc ---- */
        int cbase = (g * 64 + i) * 64 + wn * 32;
#pragma unroll
        for (int ni = 0; ni < 4; ++ni) {
            int cd0 = cbase + ni * 8 + 2 * (lane & 3);
            float c2a = __ldg(g_cn2 + cd0), c2b = __ldg(g_cn2 + cd0 + 1);
#pragma unroll
            for (int mi = 0; mi < 4; ++mi)
#pragma unroll
                for (int h = 0; h < 2; ++h) {
                    acc[mi][ni][2 * h]     = fmaf(-2.f, acc[mi][ni][2 * h],     c2a);
                    acc[mi][ni][2 * h + 1] = fmaf(-2.f, acc[mi][ni][2 * h + 1], c2b);
                }
        }
        /* min pass (keep per-thread row-min tm to gate append) */
        float tm[8];
#pragma unroll
        for (int mi = 0; mi < 4; ++mi)
#pragma unroll
            for (int h = 0; h < 2; ++h) {
                int rl = wm * 64 + mi * 16 + (lane >> 2) + h * 8;
                float m = 3.4e38f;
#pragma unroll
                for (int ni = 0; ni < 4; ++ni)
                    m = fminf(m, fminf(acc[mi][ni][2 * h], acc[mi][ni][2 * h + 1]));
                tm[mi * 2 + h] = m;
                m = fminf(m, __shfl_xor_sync(0xffffffffu, m, 1));
                m = fminf(m, __shfl_xor_sync(0xffffffffu, m, 2));
                if ((lane & 3) == 0) atomicMin(&s_amin[rl], enc_f(m));
            }
        /* append pass: no barrier — thresholds monotone, superset-safe */
#pragma unroll
        for (int mi = 0; mi < 4; ++mi)
#pragma unroll
            for (int h = 0; h < 2; ++h) {
                int rl = wm * 64 + mi * 16 + (lane >> 2) + h * 8;
                float th = dec_f(*(volatile unsigned*)&s_amin[rl]) + ww[mi * 2 + h];
                if (tm[mi * 2 + h] <= th) {
#pragma unroll
                    for (int ni = 0; ni < 4; ++ni)
#pragma unroll
                        for (int e = 0; e < 2; ++e) {
                            if (acc[mi][ni][2 * h + e] <= th) {
                                int slot = atomicAdd(&s_cnt[rl], 1);
                                if (slot < CAP)
                                    g_cand[(size_t)(bx * 128 + rl) * CAP + slot]
                                        = cbase + ni * 8 + 2 * (lane & 3) + e;
                            }
                        }
                }
            }
    }

    __syncthreads();
    if (tid < 128) g_ccount[bx * 128 + tid] = s_cnt[tid];
}

/* ================= K3: exact fp32 rescore ================= */
__global__ __launch_bounds__(256)
void rescore_kernel(const float* __restrict__ codebook) {
    int lane = threadIdx.x & 31;
    int row  = blockIdx.x * 8 + (threadIdx.x >> 5);   /* grid 2048 */
    int cnt  = g_ccount[row];

    const float4* zr = (const float4*)(g_zet + (size_t)row * EMBED_DIM);
    float4 z0 = zr[lane * 2], z1 = zr[lane * 2 + 1];

    float bv = 3.4e38f;
    int   bi = 0x7fffffff;
    int n_iter = (cnt <= CAP) ? cnt : NUM_EMBEDS;
    for (int i = 0; i < n_iter; ++i) {
        int code = (cnt <= CAP) ? g_cand[(size_t)row * CAP + i] : i;
        const float4* cr = (const float4*)(codebook + (size_t)code * EMBED_DIM);
        float4 c0 = cr[lane * 2], c1 = cr[lane * 2 + 1];
        float d = z0.x*c0.x + z0.y*c0.y + z0.z*c0.z + z0.w*c0.w
                + z1.x*c1.x + z1.y*c1.y + z1.z*c1.z + z1.w*c1.w;
#pragma unroll
        for (int o = 16; o; o >>= 1) d += __shfl_xor_sync(0xffffffffu, d, o);
        float dist = fmaf(-2.f, d, g_cn2[code]);
        if (dist < bv || (dist == bv && code < bi)) { bv = dist; bi = code; }
    }
    if (lane == 0) g_idx[row] = bi;
}

/* ================= K4: gather z_q, loss partials, histogram ================= */
__global__ __launch_bounds__(256)
void gather_kernel(const float* __restrict__ z_e,
                   const float* __restrict__ codebook,
                   float* __restrict__ out) {
    __shared__ int   sidx[64];
    __shared__ float red[256];
    int tid = threadIdx.x;
    int n0  = blockIdx.x * 64;
    if (tid < 64) sidx[tid] = g_idx[n0 + tid];
    __syncthreads();
    if (tid < 64) atomicAdd(&g_counts[sidx[tid]], 1);

    int tt = tid & 63, dd = tid >> 6;
    int b = n0 >> 10, t0 = n0 & 1023;
    size_t base = (size_t)b * EMBED_DIM * TLEN + t0 + tt;
    const float* crow = codebook + (size_t)sidx[tt] * EMBED_DIM;

    float local = 0.f;
    for (int d = dd; d < EMBED_DIM; d += 4) {
        float q = __ldg(crow + d);
        size_t a = base + (size_t)d * TLEN;
        float ze = z_e[a];
        out[a] = q;
        float df = q - ze;
        local = fmaf(df, df, local);
    }
    red[tid] = local;
    __syncthreads();
    for (int s = 128; s > 0; s >>= 1) {
        if (tid < s) red[tid] += red[tid + s];
        __syncthreads();
    }
    if (tid == 0) g_loss_part[blockIdx.x] = red[0];
}

/* ================= K5: perplexity partials ================= */
__global__ __launch_bounds__(256)
void perp_partial_kernel() {
    __shared__ float red[256];
    int tid = threadIdx.x;
    int i = blockIdx.x * 256 + tid;           /* grid 32 */
    float p = (float)g_counts[i] * (1.f / (float)NVEC);
    red[tid] = p * logf(p + 1e-10f);
    __syncthreads();
    for (int s = 128; s > 0; s >>= 1) {
        if (tid < s) red[tid] += red[tid + s];
        __syncthreads();
    }
    if (tid == 0) g_perp_part[blockIdx.x] = red[0];
}

/* ================= K6: finalize scalars ================= */
__global__ void finalize_kernel(float* __restrict__ out) {
    __shared__ float red[256];
    int tid = threadIdx.x;

    red[tid] = g_loss_part[tid];
    __syncthreads();
    for (int s = 128; s > 0; s >>= 1) {
        if (tid < s) red[tid] += red[tid + s];
        __syncthreads();
    }
    if (tid == 0) out[ZQ_ELEMS] = red[0] / (float)ZQ_ELEMS;

    red[tid] = (tid < 32) ? g_perp_part[tid] : 0.f;
    __syncthreads();
    for (int s = 128; s > 0; s >>= 1) {
        if (tid < s) red[tid] += red[tid + s];
        __syncthreads();
    }
    if (tid == 0) out[ZQ_ELEMS + 1] = expf(-red[0]);
}

/* ================= launch ================= */
extern "C" void kernel_launch(void* const* d_in, const int* in_sizes, int n_in,
                              void* d_out, int out_size) {
    const float* z_e      = (const float*)d_in[0];
    const float* codebook = (const float*)d_in[1];
    float* out = (float*)d_out;

    cudaFuncSetAttribute(gemm_screen_kernel,
                         cudaFuncAttributeMaxDynamicSharedMemorySize, SMEM_GEMM);

    init_kernel<<<1, 32>>>();
    cb_prep_kernel<<<NUM_EMBEDS / 8, 256>>>(codebook);
    ze_prep_kernel<<<NVEC / 64, 256>>>(z_e);
    gemm_screen_kernel<<<128, 256, SMEM_GEMM>>>();
    rescore_kernel<<<NVEC / 8, 256>>>(codebook);
    gather_kernel<<<NVEC / 64, 256>>>(z_e, codebook, out);
    perp_partial_kernel<<<NUM_EMBEDS / 256, 256>>>();
    finalize_kernel<<<1, 256>>>(out);
}

// round 12
// speedup vs baseline: 1.1742x; 1.1742x over previous
#include <cuda_runtime.h>
#include <cuda_bf16.h>
#include <cstdint>

#define NUM_EMBEDS 8192
#define EMBED_DIM  256
#define BATCH      16
#define TLEN       1024
#define NVEC       (BATCH * TLEN)             /* 16384 */
#define ZQ_ELEMS   (BATCH * EMBED_DIM * TLEN) /* 4194304 */
#define CAP        64

/* ---- scratch ---- */
__device__ float          g_cn2[NUM_EMBEDS];
__device__ float          g_wrow[NVEC];
__device__ int            g_cnmax_i;
__device__ int            g_ccount[NVEC];
__device__ int            g_cand[NVEC * CAP];
__device__ int            g_idx[NVEC];
__device__ int            g_counts[NUM_EMBEDS];
__device__ float          g_loss_part[256];
__device__ float          g_perp_part[32];
__device__ float          g_zet[NVEC * EMBED_DIM];         /* z_e transposed fp32 */
__device__ __nv_bfloat16  g_zbf[NVEC * EMBED_DIM];         /* z_e transposed bf16 */
__device__ __nv_bfloat16  g_cbf[NUM_EMBEDS * EMBED_DIM];   /* codebook bf16 */

/* ============================ helpers ============================ */
__device__ __forceinline__ uint32_t smem_u32(const void* p) {
    uint32_t a;
    asm("{ .reg .u64 t; cvta.to.shared.u64 t, %1; cvt.u32.u64 %0, t; }" : "=r"(a) : "l"(p));
    return a;
}
__device__ __forceinline__ unsigned enc_f(float f) {
    unsigned u = __float_as_uint(f);
    return (u & 0x80000000u) ? ~u : (u | 0x80000000u);
}
__device__ __forceinline__ float dec_f(unsigned u) {
    return (u & 0x80000000u) ? __uint_as_float(u ^ 0x80000000u) : __uint_as_float(~u);
}
__device__ __forceinline__ unsigned pack_bf2(float a, float b) {
    __nv_bfloat162 h = __floats2bfloat162_rn(a, b);
    return *(unsigned*)&h;
}

#define LDSM4(r, addr)                                                          \
    asm volatile("ldmatrix.sync.aligned.m8n8.x4.shared.b16 {%0,%1,%2,%3}, [%4];"\
        : "=r"((r)[0]), "=r"((r)[1]), "=r"((r)[2]), "=r"((r)[3]) : "r"(addr))

#define MMA_BF16(d, a, b)                                                       \
    asm volatile("mma.sync.aligned.m16n8k16.row.col.f32.bf16.bf16.f32 "         \
        "{%0,%1,%2,%3}, {%4,%5,%6,%7}, {%8,%9}, {%0,%1,%2,%3};"                 \
        : "+f"((d)[0]), "+f"((d)[1]), "+f"((d)[2]), "+f"((d)[3])                \
        : "r"((a)[0]), "r"((a)[1]), "r"((a)[2]), "r"((a)[3]),                   \
          "r"((b)[0]), "r"((b)[1]))

#define CP_ASYNC16(dst, src)                                                    \
    asm volatile("cp.async.cg.shared.global [%0], [%1], 16;" :: "r"(dst), "l"(src))
#define CP_COMMIT()  asm volatile("cp.async.commit_group;" ::: "memory")
#define CP_WAIT(n)   asm volatile("cp.async.wait_group %0;" :: "n"(n) : "memory")
#define BAR_G(id)    asm volatile("bar.sync %0, 128;" :: "r"(id) : "memory")

/* ================= P0: reset cnmax (graph-replay determinism) ================= */
__global__ void init_kernel() {
    if (threadIdx.x == 0) g_cnmax_i = 0;
}

/* ================= P1: codebook -> bf16, cn2, max ================= */
__global__ __launch_bounds__(256)
void cb_prep_kernel(const float* __restrict__ codebook) {
    int lane = threadIdx.x & 31;
    int code = blockIdx.x * 8 + (threadIdx.x >> 5);   /* grid 1024 */
    const float4* src = (const float4*)(codebook + (size_t)code * EMBED_DIM);
    float4 v0 = src[lane * 2], v1 = src[lane * 2 + 1];
    float s = v0.x*v0.x + v0.y*v0.y + v0.z*v0.z + v0.w*v0.w
            + v1.x*v1.x + v1.y*v1.y + v1.z*v1.z + v1.w*v1.w;
    uint4 u;
    u.x = pack_bf2(v0.x, v0.y); u.y = pack_bf2(v0.z, v0.w);
    u.z = pack_bf2(v1.x, v1.y); u.w = pack_bf2(v1.z, v1.w);
    ((uint4*)(g_cbf + (size_t)code * EMBED_DIM))[lane] = u;
#pragma unroll
    for (int o = 16; o; o >>= 1) s += __shfl_xor_sync(0xffffffffu, s, o);
    if (lane == 0) {
        g_cn2[code] = s;
        atomicMax(&g_cnmax_i, __float_as_int(s));
        g_counts[code] = 0;
    }
}

/* ================= P2: z_e transpose (fp32+bf16) + xnorm + window ================= */
__global__ __launch_bounds__(256)
void ze_prep_kernel(const float* __restrict__ z_e) {
    __shared__ float s[64][65];
    __shared__ float xn[4][64];
    int n0 = blockIdx.x * 64;
    int b  = n0 >> 10, t0 = n0 & 1023;
    int tx = threadIdx.x & 63, ty = threadIdx.x >> 6;
    float part = 0.f;

    for (int d0 = 0; d0 < EMBED_DIM; d0 += 64) {
        const float* src = z_e + ((size_t)b * EMBED_DIM + d0) * TLEN + t0;
#pragma unroll
        for (int j = 0; j < 16; ++j) {
            int dl = j * 4 + ty;
            s[dl][tx] = src[(size_t)dl * TLEN + tx];
        }
        __syncthreads();
#pragma unroll
        for (int j = 0; j < 16; ++j) {
            int nl = j * 4 + ty;
            float v = s[tx][nl];
            g_zet[(size_t)(n0 + nl) * EMBED_DIM + d0 + tx] = v;
            g_zbf[(size_t)(n0 + nl) * EMBED_DIM + d0 + tx] = __float2bfloat16_rn(v);
        }
#pragma unroll
        for (int j = 0; j < 16; ++j) {
            float v = s[ty * 16 + j][tx];
            part = fmaf(v, v, part);
        }
        __syncthreads();
    }
    xn[ty][tx] = part;
    __syncthreads();
    if (ty == 0) {
        float x2 = xn[0][tx] + xn[1][tx] + xn[2][tx] + xn[3][tx];
        float cnmax = __int_as_float(g_cnmax_i);
        g_wrow[n0 + tx] = 0.035f * sqrtf(x2) * sqrtf(cnmax) + 0.5f;
    }
}

/* ================= K2: persistent quad-group bf16 screening GEMM =================
 * 128 CTAs x 512 threads = 16 warps = 4 independent 4-warp groups.
 * Shared resident A (128x256). Group g owns codes [g*2048,(g+1)*2048) as 64
 * double-buffered 32-code chunks. Warp tile 32 rows x 32 codes (mi=2, ni=4).
 * warp->SMSP (w&3) gives every SMSP one warp from each group -> 4 independent
 * phases per scheduler. Per-chunk flow copied from R8 (bisect winner).
 */
#define STRH       264                       /* smem row stride halves (528 B) */
#define A_BYTES    (128 * STRH * 2)          /* 67584 */
#define BBUF_BYTES (32 * STRH * 2)           /* 16896 */
#define SM_B(g, b) (A_BYTES + ((g) * 2 + (b)) * BBUF_BYTES)
#define SM_STAT    (A_BYTES + 8 * BBUF_BYTES)   /* 202752 */
#define SMEM_GEMM  (SM_STAT + 1024)

__global__ __launch_bounds__(512, 1)
void gemm_screen_kernel() {
    extern __shared__ char sm[];
    uint32_t sb = smem_u32(sm);
    unsigned* s_amin = (unsigned*)(sm + SM_STAT);
    int*      s_cnt  = (int*)(sm + SM_STAT + 512);

    int tid = threadIdx.x, lane = tid & 31, warp = tid >> 5;
    int g  = warp >> 2;          /* group 0..3 */
    int wm = warp & 3;           /* warp-row in group: rows wm*32..wm*32+31 */
    int gt = tid & 127;          /* thread in group */
    int bar = 1 + g;
    int bx = blockIdx.x;

    if (tid < 128) { s_amin[tid] = 0xFFFFFFFFu; s_cnt[tid] = 0; }

    /* prologue: A (all 512 threads) + group's B chunks 0,1 */
    {
        const __nv_bfloat16* xa = g_zbf + (size_t)(bx * 128) * EMBED_DIM;
#pragma unroll
        for (int q = 0; q < 8; ++q) {
            int v = tid + q * 512;           /* 0..4095 */
            int row = v >> 5, c = v & 31;
            CP_ASYNC16(sb + (uint32_t)(row * STRH + c * 8) * 2,
                       (const char*)(xa + (size_t)row * EMBED_DIM + c * 8));
        }
        CP_COMMIT();
#pragma unroll
        for (int b = 0; b < 2; ++b) {
            const __nv_bfloat16* cb = g_cbf + (size_t)(g * 2048 + b * 32) * EMBED_DIM;
            uint32_t dstb = sb + SM_B(g, b);
#pragma unroll
            for (int q = 0; q < 8; ++q) {
                int v = gt + q * 128;        /* 0..1023 */
                int row = v >> 5, c = v & 31;
                CP_ASYNC16(dstb + (uint32_t)(row * STRH + c * 8) * 2,
                           (const char*)(cb + (size_t)row * EMBED_DIM + c * 8));
            }
            CP_COMMIT();
        }
        CP_WAIT(1);              /* A + own B0 complete (B1 may fly) */
        __syncthreads();
    }

    /* per-thread row windows: rows wm*32 + mi*16 + (lane>>2) + h*8 */
    float ww[4];
#pragma unroll
    for (int mi = 0; mi < 2; ++mi)
#pragma unroll
        for (int h = 0; h < 2; ++h)
            ww[mi * 2 + h] = g_wrow[bx * 128 + wm * 32 + mi * 16 + (lane >> 2) + h * 8];

    for (int i = 0; i < 64; ++i) {
        if (i) {
            if (i < 63) CP_WAIT(1); else CP_WAIT(0);
            BAR_G(bar);          /* whole group's B(i) visible */
        }
        uint32_t Bs = sb + SM_B(g, i & 1);

        float acc[2][4][4];
#pragma unroll
        for (int mi = 0; mi < 2; ++mi)
#pragma unroll
            for (int ni = 0; ni < 4; ++ni)
#pragma unroll
                for (int r = 0; r < 4; ++r) acc[mi][ni][r] = 0.f;

        /* ---- mainloop (compiler-scheduled, R8 style) ---- */
#pragma unroll
        for (int kk = 0; kk < 16; ++kk) {
            uint32_t a[2][4], bfr[4][2];
#pragma unroll
            for (int mi = 0; mi < 2; ++mi) {
                uint32_t addr = sb + (uint32_t)((wm * 32 + mi * 16 + (lane & 15)) * STRH
                                 + (lane >> 4) * 8 + kk * 16) * 2;
                LDSM4(a[mi], addr);
            }
#pragma unroll
            for (int pp = 0; pp < 2; ++pp) {
                uint32_t r4[4];
                uint32_t addr = Bs + (uint32_t)((pp * 16 + (lane & 7)
                                 + ((lane >> 4) & 1) * 8) * STRH
                                 + ((lane >> 3) & 1) * 8 + kk * 16) * 2;
                LDSM4(r4, addr);
                bfr[2 * pp][0] = r4[0];     bfr[2 * pp][1] = r4[1];
                bfr[2 * pp + 1][0] = r4[2]; bfr[2 * pp + 1][1] = r4[3];
            }
#pragma unroll
            for (int mi = 0; mi < 2; ++mi)
#pragma unroll
                for (int ni = 0; ni < 4; ++ni)
                    MMA_BF16(acc[mi][ni], a[mi], bfr[ni]);
        }

        /* ---- epilogue: dist overwrites acc ---- */
        int cbase = g * 2048 + i * 32;
#pragma unroll
        for (int ni = 0; ni < 4; ++ni) {
            int cd0 = cbase + ni * 8 + 2 * (lane & 3);
            float c2a = __ldg(g_cn2 + cd0), c2b = __ldg(g_cn2 + cd0 + 1);
#pragma unroll
            for (int mi = 0; mi < 2; ++mi)
#pragma unroll
                for (int h = 0; h < 2; ++h) {
                    acc[mi][ni][2 * h]     = fmaf(-2.f, acc[mi][ni][2 * h],     c2a);
                    acc[mi][ni][2 * h + 1] = fmaf(-2.f, acc[mi][ni][2 * h + 1], c2b);
                }
        }
        /* min pass (keep per-thread row-min tm to gate append) */
        float tm[4];
#pragma unroll
        for (int mi = 0; mi < 2; ++mi)
#pragma unroll
            for (int h = 0; h < 2; ++h) {
                int rl = wm * 32 + mi * 16 + (lane >> 2) + h * 8;
                float m = 3.4e38f;
#pragma unroll
                for (int ni = 0; ni < 4; ++ni)
                    m = fminf(m, fminf(acc[mi][ni][2 * h], acc[mi][ni][2 * h + 1]));
                tm[mi * 2 + h] = m;
                m = fminf(m, __shfl_xor_sync(0xffffffffu, m, 1));
                m = fminf(m, __shfl_xor_sync(0xffffffffu, m, 2));
                if ((lane & 3) == 0) atomicMin(&s_amin[rl], enc_f(m));
            }
        BAR_G(bar);              /* mins visible; all group ldsm done */

        /* append pass: gated by per-thread min (superset-safe) */
#pragma unroll
        for (int mi = 0; mi < 2; ++mi)
#pragma unroll
            for (int h = 0; h < 2; ++h) {
                int rl = wm * 32 + mi * 16 + (lane >> 2) + h * 8;
                float th = dec_f(s_amin[rl]) + ww[mi * 2 + h];
                if (tm[mi * 2 + h] <= th) {
#pragma unroll
                    for (int ni = 0; ni < 4; ++ni)
#pragma unroll
                        for (int e = 0; e < 2; ++e) {
                            if (acc[mi][ni][2 * h + e] <= th) {
                                int slot = atomicAdd(&s_cnt[rl], 1);
                                if (slot < CAP)
                                    g_cand[(size_t)(bx * 128 + rl) * CAP + slot]
                                        = cbase + ni * 8 + 2 * (lane & 3) + e;
                            }
                        }
                }
            }

        /* issue next-next chunk load into the buffer just freed (R8 position) */
        if (i < 62) {
            const __nv_bfloat16* cb = g_cbf + (size_t)(g * 2048 + (i + 2) * 32) * EMBED_DIM;
            uint32_t dstb = sb + SM_B(g, i & 1);
#pragma unroll
            for (int q = 0; q < 8; ++q) {
                int v = gt + q * 128;
                int row = v >> 5, c = v & 31;
                CP_ASYNC16(dstb + (uint32_t)(row * STRH + c * 8) * 2,
                           (const char*)(cb + (size_t)row * EMBED_DIM + c * 8));
            }
            CP_COMMIT();
        }
    }

    __syncthreads();
    if (tid < 128) g_ccount[bx * 128 + tid] = s_cnt[tid];
}

/* ================= K3: exact fp32 rescore ================= */
__global__ __launch_bounds__(256)
void rescore_kernel(const float* __restrict__ codebook) {
    int lane = threadIdx.x & 31;
    int row  = blockIdx.x * 8 + (threadIdx.x >> 5);   /* grid 2048 */
    int cnt  = g_ccount[row];

    const float4* zr = (const float4*)(g_zet + (size_t)row * EMBED_DIM);
    float4 z0 = zr[lane * 2], z1 = zr[lane * 2 + 1];

    float bv = 3.4e38f;
    int   bi = 0x7fffffff;
    int n_iter = (cnt <= CAP) ? cnt : NUM_EMBEDS;
    for (int i = 0; i < n_iter; ++i) {
        int code = (cnt <= CAP) ? g_cand[(size_t)row * CAP + i] : i;
        const float4* cr = (const float4*)(codebook + (size_t)code * EMBED_DIM);
        float4 c0 = cr[lane * 2], c1 = cr[lane * 2 + 1];
        float d = z0.x*c0.x + z0.y*c0.y + z0.z*c0.z + z0.w*c0.w
                + z1.x*c1.x + z1.y*c1.y + z1.z*c1.z + z1.w*c1.w;
#pragma unroll
        for (int o = 16; o; o >>= 1) d += __shfl_xor_sync(0xffffffffu, d, o);
        float dist = fmaf(-2.f, d, g_cn2[code]);
        if (dist < bv || (dist == bv && code < bi)) { bv = dist; bi = code; }
    }
    if (lane == 0) g_idx[row] = bi;
}

/* ================= K4: gather z_q, loss partials, histogram ================= */
__global__ __launch_bounds__(256)
void gather_kernel(const float* __restrict__ z_e,
                   const float* __restrict__ codebook,
                   float* __restrict__ out) {
    __shared__ int   sidx[64];
    __shared__ float red[256];
    int tid = threadIdx.x;
    int n0  = blockIdx.x * 64;
    if (tid < 64) sidx[tid] = g_idx[n0 + tid];
    __syncthreads();
    if (tid < 64) atomicAdd(&g_counts[sidx[tid]], 1);

    int tt = tid & 63, dd = tid >> 6;
    int b = n0 >> 10, t0 = n0 & 1023;
    size_t base = (size_t)b * EMBED_DIM * TLEN + t0 + tt;
    const float* crow = codebook + (size_t)sidx[tt] * EMBED_DIM;

    float local = 0.f;
    for (int d = dd; d < EMBED_DIM; d += 4) {
        float q = __ldg(crow + d);
        size_t a = base + (size_t)d * TLEN;
        float ze = z_e[a];
        out[a] = q;
        float df = q - ze;
        local = fmaf(df, df, local);
    }
    red[tid] = local;
    __syncthreads();
    for (int s = 128; s > 0; s >>= 1) {
        if (tid < s) red[tid] += red[tid + s];
        __syncthreads();
    }
    if (tid == 0) g_loss_part[blockIdx.x] = red[0];
}

/* ================= K5: perplexity partials ================= */
__global__ __launch_bounds__(256)
void perp_partial_kernel() {
    __shared__ float red[256];
    int tid = threadIdx.x;
    int i = blockIdx.x * 256 + tid;           /* grid 32 */
    float p = (float)g_counts[i] * (1.f / (float)NVEC);
    red[tid] = p * logf(p + 1e-10f);
    __syncthreads();
    for (int s = 128; s > 0; s >>= 1) {
        if (tid < s) red[tid] += red[tid + s];
        __syncthreads();
    }
    if (tid == 0) g_perp_part[blockIdx.x] = red[0];
}

/* ================= K6: finalize scalars ================= */
__global__ void finalize_kernel(float* __restrict__ out) {
    __shared__ float red[256];
    int tid = threadIdx.x;

    red[tid] = g_loss_part[tid];
    __syncthreads();
    for (int s = 128; s > 0; s >>= 1) {
        if (tid < s) red[tid] += red[tid + s];
        __syncthreads();
    }
    if (tid == 0) out[ZQ_ELEMS] = red[0] / (float)ZQ_ELEMS;

    red[tid] = (tid < 32) ? g_perp_part[tid] : 0.f;
    __syncthreads();
    for (int s = 128; s > 0; s >>= 1) {
        if (tid < s) red[tid] += red[tid + s];
        __syncthreads();
    }
    if (tid == 0) out[ZQ_ELEMS + 1] = expf(-red[0]);
}

/* ================= launch ================= */
extern "C" void kernel_launch(void* const* d_in, const int* in_sizes, int n_in,
                              void* d_out, int out_size) {
    const float* z_e      = (const float*)d_in[0];
    const float* codebook = (const float*)d_in[1];
    float* out = (float*)d_out;

    cudaFuncSetAttribute(gemm_screen_kernel,
                         cudaFuncAttributeMaxDynamicSharedMemorySize, SMEM_GEMM);

    init_kernel<<<1, 32>>>();
    cb_prep_kernel<<<NUM_EMBEDS / 8, 256>>>(codebook);
    ze_prep_kernel<<<NVEC / 64, 256>>>(z_e);
    gemm_screen_kernel<<<128, 512, SMEM_GEMM>>>();
    rescore_kernel<<<NVEC / 8, 256>>>(codebook);
    gather_kernel<<<NVEC / 64, 256>>>(z_e, codebook, out);
    perp_partial_kernel<<<NUM_EMBEDS / 256, 256>>>();
    finalize_kernel<<<1, 256>>>(out);
}